// round 5
// baseline (speedup 1.0000x reference)
#include <cuda_runtime.h>

// LIF recurrence, forward spikes only.
// x: [T=32, B, D] fp32, out: same shape, spikes in {0.0, 1.0}.
//
//   mem_t   = dec_{t-1} + x_t
//   spike_t = mem_t > 0.5
//   dec_t   = spike_t ? 0 : mem_t * 0.25      (carried state, dec_{-1}=0)
//
// Touch-once HBM stream (268 MB). R2-R4 taught: occ*MLP is conserved when
// buying MLP with registers, but PIPELINING (loads of next chunk issued
// before compute of current) adds real DRAM% at any occ. This round: keep
// the never-drain pipeline but shrink buffers to depth 4 (regs ~60) so
// occupancy recovers to 3 blocks/SM — continuous load issue AND enough
// warps to hide each other's compute/store phases.

#define THRESH 0.5f
#define DECAY  0.25f

__device__ __forceinline__ void load4(float4 (&b)[4], const float4* __restrict__ p,
                                      long st)
{
    #pragma unroll
    for (int k = 0; k < 4; k++)
        b[k] = __ldcs(p + (long)k * st);
}

__device__ __forceinline__ void comp4(const float4 (&b)[4], float4& dec,
                                      float4* __restrict__ op, long st)
{
    #pragma unroll
    for (int k = 0; k < 4; k++) {
        float4 m, s;
        m.x = dec.x + b[k].x;
        m.y = dec.y + b[k].y;
        m.z = dec.z + b[k].z;
        m.w = dec.w + b[k].w;

        s.x = (m.x > THRESH) ? 1.0f : 0.0f;
        s.y = (m.y > THRESH) ? 1.0f : 0.0f;
        s.z = (m.z > THRESH) ? 1.0f : 0.0f;
        s.w = (m.w > THRESH) ? 1.0f : 0.0f;

        dec.x = (m.x > THRESH) ? 0.0f : m.x * DECAY;
        dec.y = (m.y > THRESH) ? 0.0f : m.y * DECAY;
        dec.z = (m.z > THRESH) ? 0.0f : m.z * DECAY;
        dec.w = (m.w > THRESH) ? 0.0f : m.w * DECAY;

        __stcs(op + (long)k * st, s);
    }
}

__global__ __launch_bounds__(256) void lif_kernel(
    const float4* __restrict__ x,
    float4* __restrict__ out,
    int chains4)   // BD / 4
{
    int i = blockIdx.x * blockDim.x + threadIdx.x;
    const long st = chains4;
    const float4* __restrict__ xp = x + i;
    float4* __restrict__       op = out + i;

    float4 A[4], B[4];
    float4 dec = make_float4(0.0f, 0.0f, 0.0f, 0.0f);

    // 8 chunks of 4 timesteps, ping-pong A/B, loads always one chunk ahead.
    load4(A, xp + 0 * st, st);
    load4(B, xp + 4 * st, st);
    comp4(A, dec, op + 0 * st, st);
    load4(A, xp + 8 * st, st);
    comp4(B, dec, op + 4 * st, st);
    load4(B, xp + 12 * st, st);
    comp4(A, dec, op + 8 * st, st);
    load4(A, xp + 16 * st, st);
    comp4(B, dec, op + 12 * st, st);
    load4(B, xp + 20 * st, st);
    comp4(A, dec, op + 16 * st, st);
    load4(A, xp + 24 * st, st);
    comp4(B, dec, op + 20 * st, st);
    load4(B, xp + 28 * st, st);
    comp4(A, dec, op + 24 * st, st);
    comp4(B, dec, op + 28 * st, st);
}

extern "C" void kernel_launch(void* const* d_in, const int* in_sizes, int n_in,
                              void* d_out, int out_size)
{
    const float* x = (const float*)d_in[0];
    float* out = (float*)d_out;

    const int T = 32;
    int total = in_sizes[0];        // T * B * D
    int BD = total / T;             // 1,048,576
    int chains4 = BD / 4;           // 262,144

    int threads = 256;
    int blocks = chains4 / threads; // exact: 1024
    lif_kernel<<<blocks, threads>>>((const float4*)x, (float4*)out, chains4);
}